// round 2
// baseline (speedup 1.0000x reference)
#include <cuda_runtime.h>

#define V 8192
#define B 64
#define M3 (3 * V)        // 24576 flattened (j,k) dim
#define STRIDE (V + 2)
#define MTILE 128
#define SPLITK 3
#define KC 2731           // ceil(V / SPLITK)
#define U 8               // i-steps per SMEM chunk

typedef unsigned long long ull;

// Packed f32x2 FMA: d = a*b + c (elementwise on 2 packed floats)
#define FFMA2(d, a, b, c) \
    asm("fma.rn.f32x2 %0, %1, %2, %3;" : "=l"(d) : "l"(a), "l"(b), "l"(c))

// Duplicated transpose of func: fTd[i*B + b] = (f[b,i], f[b,i])  -> 4 MB, L2-resident
__device__ float2 g_fTd[V * B];

// ---------------------------------------------------------------------------
// Prep: build g_fTd, write op_mask into out (also un-poisons out).
// ---------------------------------------------------------------------------
__global__ void prep_kernel(const float* __restrict__ func, float* __restrict__ out) {
    int idx = blockIdx.x * blockDim.x + threadIdx.x;   // 0 .. V*B-1
    int b = idx >> 13;            // / V
    int i = idx & (V - 1);
    float v = func[b * STRIDE + i];
    g_fTd[i * B + b] = make_float2(v, v);
    if (idx < B) {
        const float QI = 1000000000.0f;
        float a1 = func[idx * STRIDE + V];
        float a2 = func[idx * STRIDE + V + 1];
        out[idx * 3 + 0] = a1 * -QI;
        out[idx * 3 + 1] = (1.0f - (1.0f - a1) * (1.0f - a2)) * -QI;
        out[idx * 3 + 2] = 0.0f;
    }
}

// ---------------------------------------------------------------------------
// Main: D[m,b] = sum_i C_flat[i,m] * f[b,i]   (per M-tile of 128, split-K)
// fused epilogue: out[b, m%3] += D[m,b] * arg[b, m/3]
// ---------------------------------------------------------------------------
__global__ __launch_bounds__(256, 2)
void cooc_gemm(const float* __restrict__ cooc,
               const float* __restrict__ arg,
               float* __restrict__ out) {
    __shared__ ulonglong2 Cs[2][U][32];   // 8 rows x 512B
    __shared__ ulonglong2 Fs[2][U][32];   // 8 rows x 512B (64 duplicated float2)

    const int tid  = threadIdx.x;
    const int il   = tid >> 5;       // 0..7  chunk row for loads
    const int lane = tid & 31;       // float4 index within row
    const int tm   = tid & 15;       // m-subtile: 8 m's
    const int tb   = tid >> 4;       // b-subtile: 4 b's

    const int m0   = blockIdx.x * MTILE;
    const int i0   = blockIdx.y * KC;
    const int iend = min(i0 + KC, V);
    const int nc   = (iend - i0 + U - 1) / U;

    ull acc[4][4];
    #pragma unroll
    for (int p = 0; p < 4; p++)
        #pragma unroll
        for (int q = 0; q < 4; q++) acc[p][q] = 0ull;   // bits of (0.f,0.f)

    ulonglong2 rc, rf;
    // prefetch chunk 0
    {
        int i = i0 + il;
        if (i < iend) {
            rc = *(const ulonglong2*)(cooc + (size_t)i * M3 + m0 + lane * 4);
            rf = *(const ulonglong2*)((const char*)g_fTd + (size_t)i * (B * 8) + lane * 16);
        } else { rc.x = rc.y = 0ull; rf.x = rf.y = 0ull; }
    }

    int buf = 0;
    for (int ic = 0; ic < nc; ic++) {
        Cs[buf][il][lane] = rc;
        Fs[buf][il][lane] = rf;
        __syncthreads();

        if (ic + 1 < nc) {
            int i = i0 + (ic + 1) * U + il;
            if (i < iend) {
                rc = *(const ulonglong2*)(cooc + (size_t)i * M3 + m0 + lane * 4);
                rf = *(const ulonglong2*)((const char*)g_fTd + (size_t)i * (B * 8) + lane * 16);
            } else { rc.x = rc.y = 0ull; rf.x = rf.y = 0ull; }
        }

        #pragma unroll
        for (int s = 0; s < U; s++) {
            ulonglong2 ca = Cs[buf][s][tm * 2];
            ulonglong2 cb = Cs[buf][s][tm * 2 + 1];
            ulonglong2 fa = Fs[buf][s][tb * 2];
            ulonglong2 fb = Fs[buf][s][tb * 2 + 1];
            ull c[4] = {ca.x, ca.y, cb.x, cb.y};
            ull f[4] = {fa.x, fa.y, fb.x, fb.y};
            #pragma unroll
            for (int p = 0; p < 4; p++)
                #pragma unroll
                for (int q = 0; q < 4; q++)
                    FFMA2(acc[p][q], c[p], f[q], acc[p][q]);
        }
        buf ^= 1;
    }

    // ---- fused epilogue: weight by arg and reduce to out[b,k] ----
    float po0[4] = {0, 0, 0, 0}, po1[4] = {0, 0, 0, 0}, po2[4] = {0, 0, 0, 0};
    #pragma unroll
    for (int p = 0; p < 4; p++) {
        #pragma unroll
        for (int e = 0; e < 2; e++) {
            int m = m0 + tm * 8 + p * 2 + e;
            int j = m / 3;
            int k = m - 3 * j;
            #pragma unroll
            for (int q = 0; q < 4; q++) {
                int b = tb * 4 + q;
                float2 vv = *(float2*)&acc[p][q];
                float d = e ? vv.y : vv.x;
                float av = __ldg(&arg[b * STRIDE + j]);
                float t = d * av;
                if (k == 0) po0[q] += t;
                else if (k == 1) po1[q] += t;
                else po2[q] += t;
            }
        }
    }

    __syncthreads();
    float* os = (float*)Cs;          // reuse SMEM for 192-float reduction
    if (tid < B * 3) os[tid] = 0.0f;
    __syncthreads();
    #pragma unroll
    for (int q = 0; q < 4; q++) {
        int b = tb * 4 + q;
        atomicAdd(&os[b * 3 + 0], po0[q]);
        atomicAdd(&os[b * 3 + 1], po1[q]);
        atomicAdd(&os[b * 3 + 2], po2[q]);
    }
    __syncthreads();
    if (tid < B * 3) atomicAdd(&out[tid], os[tid]);
}

// ---------------------------------------------------------------------------
extern "C" void kernel_launch(void* const* d_in, const int* in_sizes, int n_in,
                              void* d_out, int out_size) {
    const float* func = (const float*)d_in[0];
    const float* arg  = (const float*)d_in[1];
    const float* cooc = (const float*)d_in[2];
    float* out = (float*)d_out;

    prep_kernel<<<(V * B) / 256, 256>>>(func, out);
    cooc_gemm<<<dim3(M3 / MTILE, SPLITK), 256>>>(cooc, arg, out);
}

// round 4
// speedup vs baseline: 4.0418x; 4.0418x over previous
#include <cuda_runtime.h>
#include <cstdint>

#define V 8192
#define NB 64
#define M3 24576
#define STRIDE 8194
#define MT 256
#define GRID 96            // 24576 / 256
#define KC 32
#define NSTAGE 256         // 8192 / 32

#define PC 264             // Cs pitch (floats): quad stride 264%32=8 banks -> conflict-free frags
#define PF 72              // Fs pitch: 72%32=8
#define PD 72              // Ds pitch (epilogue)

#define CS_FLOATS (KC * PC)              // 8448
#define FS_FLOATS (KC * PF)              // 2304
#define BUF_FLOATS (CS_FLOATS + FS_FLOATS)   // 10752
#define SMEM_FLOATS (2 * BUF_FLOATS)     // 21504 floats = 86016 B
#define SMEM_DYN (SMEM_FLOATS * 4)

// m16n8k8 tf32 HMMA (portable PTX, works on compute_103 non-'a')
#define MMA_TF32(d, a0, a1, a2, a3, b0, b1)                                   \
    asm volatile("mma.sync.aligned.m16n8k8.row.col.f32.tf32.tf32.f32 "        \
        "{%0,%1,%2,%3}, {%4,%5,%6,%7}, {%8,%9}, {%0,%1,%2,%3};"               \
        : "+f"((d)[0]), "+f"((d)[1]), "+f"((d)[2]), "+f"((d)[3])              \
        : "r"(a0), "r"(a1), "r"(a2), "r"(a3), "r"(b0), "r"(b1))

__device__ float g_fT[V * NB];   // 2 MB, L2-resident: f transposed [i][b], tf32-rounded

__device__ __forceinline__ float rn_tf32(float x) {   // round-half-up to tf32 grid
    return __uint_as_float(__float_as_uint(x) + 0x1000u);
}
__device__ __forceinline__ unsigned fbits(float x) { return __float_as_uint(x); }

// ---------------------------------------------------------------------------
// Prep: transpose func -> g_fT (tf32-rounded); write op_mask into out.
// ---------------------------------------------------------------------------
__global__ void prep_kernel(const float* __restrict__ func, float* __restrict__ out) {
    int idx = blockIdx.x * 256 + threadIdx.x;    // < V*NB
    int i = idx >> 6;
    int b = idx & 63;
    g_fT[idx] = rn_tf32(func[b * STRIDE + i]);
    if (idx < NB) {
        const float QI = 1000000000.0f;
        float a1 = func[idx * STRIDE + V];
        float a2 = func[idx * STRIDE + V + 1];
        out[idx * 3 + 0] = a1 * -QI;
        out[idx * 3 + 1] = (1.0f - (1.0f - a1) * (1.0f - a2)) * -QI;
        out[idx * 3 + 2] = 0.0f;
    }
}

// ---------------------------------------------------------------------------
// Main: warp-level tf32 mma.sync GEMM + fused arg-weighted reduction.
// ---------------------------------------------------------------------------
__global__ __launch_bounds__(256, 1)
void cooc_mma(const float* __restrict__ cooc,
              const float* __restrict__ arg,
              float* __restrict__ out) {
    extern __shared__ float sm[];

    const int tid  = threadIdx.x;
    const int lane = tid & 31;
    const int wid  = tid >> 5;
    const int mg   = wid & 3;          // m-group: 64 m each
    const int kg   = wid >> 2;         // k-group: 16 k each within stage
    const int quad = lane & 3;
    const int qid  = lane >> 2;
    const int m0   = blockIdx.x * MT;

    float acc[4][8][4];
    #pragma unroll
    for (int mt = 0; mt < 4; mt++)
        #pragma unroll
        for (int nt = 0; nt < 8; nt++)
            #pragma unroll
            for (int r = 0; r < 4; r++) acc[mt][nt][r] = 0.0f;

    // ---- register prefetch of stage 0 ----
    float4 cr[8], fr[2];
    #pragma unroll
    for (int it = 0; it < 8; it++) {
        int flat = it * 256 + tid;
        int row = flat >> 6, c4 = flat & 63;
        cr[it] = __ldg((const float4*)(cooc + (size_t)row * M3 + m0 + c4 * 4));
    }
    #pragma unroll
    for (int it = 0; it < 2; it++) {
        int flat = it * 256 + tid;
        fr[it] = *(const float4*)(g_fT + flat * 4);
    }

    for (int s = 0; s < NSTAGE; s++) {
        float* buf = sm + (s & 1) * BUF_FLOATS;

        // ---- STS stage s (round C to tf32 half-up) ----
        #pragma unroll
        for (int it = 0; it < 8; it++) {
            int flat = it * 256 + tid;
            int row = flat >> 6, c4 = flat & 63;
            float4 v = cr[it];
            v.x = rn_tf32(v.x); v.y = rn_tf32(v.y);
            v.z = rn_tf32(v.z); v.w = rn_tf32(v.w);
            *(float4*)(buf + row * PC + c4 * 4) = v;
        }
        #pragma unroll
        for (int it = 0; it < 2; it++) {
            int flat = it * 256 + tid;
            int row = flat >> 4, c4 = flat & 15;
            *(float4*)(buf + CS_FLOATS + row * PF + c4 * 4) = fr[it];
        }
        __syncthreads();

        // ---- prefetch stage s+1 ----
        if (s + 1 < NSTAGE) {
            #pragma unroll
            for (int it = 0; it < 8; it++) {
                int flat = it * 256 + tid;
                int row = flat >> 6, c4 = flat & 63;
                cr[it] = __ldg((const float4*)(cooc + (size_t)((s + 1) * KC + row) * M3 + m0 + c4 * 4));
            }
            #pragma unroll
            for (int it = 0; it < 2; it++) {
                int flat = it * 256 + tid;
                fr[it] = *(const float4*)(g_fT + (s + 1) * (KC * NB) + flat * 4);
            }
        }

        // ---- compute stage s: this warp handles k = kg*16 .. +15 ----
        const float* csA = buf + quad * PC + mg * 64 + qid;
        const float* fsB = buf + CS_FLOATS + quad * PF + qid;
        #pragma unroll
        for (int kk = 0; kk < 2; kk++) {
            const int kb = kg * 16 + kk * 8;
            const float* ca = csA + kb * PC;
            const float* fb = fsB + kb * PF;
            unsigned b0[8], b1[8];
            #pragma unroll
            for (int nt = 0; nt < 8; nt++) {
                b0[nt] = fbits(fb[nt * 8]);
                b1[nt] = fbits(fb[4 * PF + nt * 8]);
            }
            #pragma unroll
            for (int mt = 0; mt < 4; mt++) {
                unsigned a0 = fbits(ca[mt * 16]);
                unsigned a1 = fbits(ca[mt * 16 + 8]);
                unsigned a2 = fbits(ca[4 * PC + mt * 16]);
                unsigned a3 = fbits(ca[4 * PC + mt * 16 + 8]);
                #pragma unroll
                for (int nt = 0; nt < 8; nt++)
                    MMA_TF32(acc[mt][nt], a0, a1, a2, a3, b0[nt], b1[nt]);
            }
        }
        __syncthreads();
    }

    // =================== epilogue ===================
    float* Ds = sm;                         // 256 x PD floats (73728 B)

    if (kg == 0) {
        #pragma unroll
        for (int mt = 0; mt < 4; mt++) {
            int ml = mg * 64 + mt * 16 + qid;
            #pragma unroll
            for (int nt = 0; nt < 8; nt++) {
                int bb = nt * 8 + 2 * quad;
                Ds[ml * PD + bb]           = acc[mt][nt][0];
                Ds[ml * PD + bb + 1]       = acc[mt][nt][1];
                Ds[(ml + 8) * PD + bb]     = acc[mt][nt][2];
                Ds[(ml + 8) * PD + bb + 1] = acc[mt][nt][3];
            }
        }
    }
    __syncthreads();
    if (kg == 1) {
        #pragma unroll
        for (int mt = 0; mt < 4; mt++) {
            int ml = mg * 64 + mt * 16 + qid;
            #pragma unroll
            for (int nt = 0; nt < 8; nt++) {
                int bb = nt * 8 + 2 * quad;
                Ds[ml * PD + bb]           += acc[mt][nt][0];
                Ds[ml * PD + bb + 1]       += acc[mt][nt][1];
                Ds[(ml + 8) * PD + bb]     += acc[mt][nt][2];
                Ds[(ml + 8) * PD + bb + 1] += acc[mt][nt][3];
            }
        }
    }
    __syncthreads();

    // column reduction: thread owns (b = tid&63, m-quarter = tid>>6)
    float* sout = sm + 256 * PD;            // 192 floats, beyond Ds
    if (tid < 192) sout[tid] = 0.0f;

    {
        const int bb = tid & 63;
        const int mq = tid >> 6;
        const float* argb = arg + bb * STRIDE;
        float po0 = 0.f, po1 = 0.f, po2 = 0.f;
        #pragma unroll 4
        for (int mm = 0; mm < 64; mm++) {
            int ml = mq * 64 + mm;
            int m = m0 + ml;
            unsigned j = (unsigned)m / 3u;
            int k = m - 3 * (int)j;
            float t = Ds[ml * PD + bb] * __ldg(argb + j);
            if (k == 0) po0 += t;
            else if (k == 1) po1 += t;
            else po2 += t;
        }
        __syncthreads();
        atomicAdd(&sout[bb * 3 + 0], po0);
        atomicAdd(&sout[bb * 3 + 1], po1);
        atomicAdd(&sout[bb * 3 + 2], po2);
    }
    __syncthreads();
    if (tid < 192) atomicAdd(&out[tid], sout[tid]);
}

// ---------------------------------------------------------------------------
extern "C" void kernel_launch(void* const* d_in, const int* in_sizes, int n_in,
                              void* d_out, int out_size) {
    const float* func = (const float*)d_in[0];
    const float* arg  = (const float*)d_in[1];
    const float* cooc = (const float*)d_in[2];
    float* out = (float*)d_out;

    cudaFuncSetAttribute(cooc_mma, cudaFuncAttributeMaxDynamicSharedMemorySize, SMEM_DYN);

    prep_kernel<<<(V * NB) / 256, 256>>>(func, out);
    cooc_mma<<<GRID, 256, SMEM_DYN>>>(cooc, arg, out);
}

// round 5
// speedup vs baseline: 4.3731x; 1.0820x over previous
#include <cuda_runtime.h>
#include <cstdint>

#define V 8192
#define NB 64
#define M3 24576
#define STRIDE 8194
#define MT 128
#define GRID 192           // 24576 / 128
#define KC 32
#define NSTAGE 256         // 8192 / 32
#define NST 4              // pipeline stages

#define PC 136             // C tile pitch (floats): 136%32=8 -> conflict-free frag reads
#define PF 72              // f tile pitch: 72%32=8
#define PD 72              // epilogue pitch

#define CS_FLOATS (KC * PC)                  // 4352
#define FS_FLOATS (KC * PF)                  // 2304
#define SB_FLOATS (CS_FLOATS + FS_FLOATS)    // 6656
#define SMEM_DYN (NST * SB_FLOATS * 4)       // 106496 B

// m16n8k8 tf32 HMMA (portable PTX, works through compute_103 non-'a')
#define MMA_TF32(d, a0, a1, a2, a3, b0, b1)                                   \
    asm volatile("mma.sync.aligned.m16n8k8.row.col.f32.tf32.tf32.f32 "        \
        "{%0,%1,%2,%3}, {%4,%5,%6,%7}, {%8,%9}, {%0,%1,%2,%3};"               \
        : "+f"((d)[0]), "+f"((d)[1]), "+f"((d)[2]), "+f"((d)[3])              \
        : "r"(a0), "r"(a1), "r"(a2), "r"(a3), "r"(b0), "r"(b1))

#define CP16(dst_u32, src_gl) \
    asm volatile("cp.async.cg.shared.global [%0], [%1], 16;" :: "r"(dst_u32), "l"(src_gl))
#define CP_COMMIT()  asm volatile("cp.async.commit_group;" ::: "memory")
#define CP_WAIT2()   asm volatile("cp.async.wait_group 2;" ::: "memory")
#define CP_WAIT0()   asm volatile("cp.async.wait_group 0;" ::: "memory")

__device__ float g_fT[V * NB];   // 2 MB, L2-resident: f transposed [i][b], tf32-rounded

__device__ __forceinline__ float rn_tf32(float x) {   // round-half-up onto tf32 grid
    return __uint_as_float(__float_as_uint(x) + 0x1000u);
}
__device__ __forceinline__ unsigned fbits_rn(float x) { return __float_as_uint(x) + 0x1000u; }
__device__ __forceinline__ unsigned fbits(float x)    { return __float_as_uint(x); }

// ---------------------------------------------------------------------------
// Prep: transpose func -> g_fT (tf32-rounded); write op_mask into out.
// ---------------------------------------------------------------------------
__global__ void prep_kernel(const float* __restrict__ func, float* __restrict__ out) {
    int idx = blockIdx.x * 256 + threadIdx.x;    // < V*NB
    int i = idx >> 6;
    int b = idx & 63;
    g_fT[idx] = rn_tf32(func[b * STRIDE + i]);
    if (idx < NB) {
        const float QI = 1000000000.0f;
        float a1 = func[idx * STRIDE + V];
        float a2 = func[idx * STRIDE + V + 1];
        out[idx * 3 + 0] = a1 * -QI;
        out[idx * 3 + 1] = (1.0f - (1.0f - a1) * (1.0f - a2)) * -QI;
        out[idx * 3 + 2] = 0.0f;
    }
}

// ---------------------------------------------------------------------------
// Main: cp.async 4-stage pipeline + tf32 mma.sync + fused arg-weighted reduce.
// ---------------------------------------------------------------------------
__global__ __launch_bounds__(256, 2)
void cooc_mma(const float* __restrict__ cooc,
              const float* __restrict__ arg,
              float* __restrict__ out) {
    extern __shared__ float sm[];

    const int tid  = threadIdx.x;
    const int lane = tid & 31;
    const int wid  = tid >> 5;
    const int mg   = wid & 3;          // m-group: 32 m each
    const int kg   = wid >> 2;         // k-group: 16 k each within stage
    const int quad = lane & 3;
    const int qid  = lane >> 2;
    const int m0   = blockIdx.x * MT;

    unsigned smem_base;
    asm("{ .reg .u64 t; cvta.to.shared.u64 t, %1; cvt.u32.u64 %0, t; }"
        : "=r"(smem_base) : "l"(sm));

    // per-thread copy slots:
    //   C tile: 32 rows x 128 floats = 1024 x 16B chunks -> 4 per thread
    //   f tile: 32 rows x  64 floats =  512 x 16B chunks -> 2 per thread
    const int c_row = tid >> 5 | 0;                 // placeholder (recomputed below)
    (void)c_row;
    int crow[4], cc16[4];
    #pragma unroll
    for (int it = 0; it < 4; it++) {
        int flat = it * 256 + tid;
        crow[it] = flat >> 5;
        cc16[it] = flat & 31;
    }
    int frow[2], fc16[2];
    #pragma unroll
    for (int it = 0; it < 2; it++) {
        int flat = it * 256 + tid;
        frow[it] = flat >> 4;
        fc16[it] = flat & 15;
    }

    const char* cooc_g = (const char*)__cvta_generic_to_global(cooc);
    const char* fT_g   = (const char*)__cvta_generic_to_global(g_fT);

    float acc[2][8][4];
    #pragma unroll
    for (int mt = 0; mt < 2; mt++)
        #pragma unroll
        for (int nt = 0; nt < 8; nt++)
            #pragma unroll
            for (int r = 0; r < 4; r++) acc[mt][nt][r] = 0.0f;

    // issue one stage's copies
    auto issue = [&](int s) {
        unsigned buf = smem_base + (s & (NST - 1)) * (SB_FLOATS * 4);
        #pragma unroll
        for (int it = 0; it < 4; it++) {
            const char* src = cooc_g + ((size_t)(s * KC + crow[it]) * M3 + m0 + cc16[it] * 4) * 4;
            CP16(buf + (crow[it] * PC + cc16[it] * 4) * 4, src);
        }
        unsigned fb = buf + CS_FLOATS * 4;
        #pragma unroll
        for (int it = 0; it < 2; it++) {
            const char* src = fT_g + ((size_t)s * (KC * NB) + frow[it] * NB + fc16[it] * 4) * 4;
            CP16(fb + (frow[it] * PF + fc16[it] * 4) * 4, src);
        }
    };

    // prologue: stages 0..2
    #pragma unroll
    for (int p = 0; p < NST - 1; p++) { issue(p); CP_COMMIT(); }

    for (int s = 0; s < NSTAGE; s++) {
        CP_WAIT2();
        __syncthreads();

        if (s + NST - 1 < NSTAGE) issue(s + NST - 1);
        CP_COMMIT();                       // empty group near the tail keeps wait_group semantics

        const float* buf = sm + (s & (NST - 1)) * SB_FLOATS;
        const float* csA = buf + quad * PC + mg * 32 + qid;
        const float* fsB = buf + CS_FLOATS + quad * PF + qid;

        #pragma unroll
        for (int kk = 0; kk < 2; kk++) {
            const int kb = kg * 16 + kk * 8;
            const float* ca = csA + kb * PC;
            const float* fb = fsB + kb * PF;
            unsigned b0[8], b1[8];
            #pragma unroll
            for (int nt = 0; nt < 8; nt++) {
                b0[nt] = fbits(fb[nt * 8]);            // f pre-rounded in prep
                b1[nt] = fbits(fb[4 * PF + nt * 8]);
            }
            #pragma unroll
            for (int mt = 0; mt < 2; mt++) {
                unsigned a0 = fbits_rn(ca[mt * 16]);   // round C -> tf32 in-register
                unsigned a1 = fbits_rn(ca[mt * 16 + 8]);
                unsigned a2 = fbits_rn(ca[4 * PC + mt * 16]);
                unsigned a3 = fbits_rn(ca[4 * PC + mt * 16 + 8]);
                #pragma unroll
                for (int nt = 0; nt < 8; nt++)
                    MMA_TF32(acc[mt][nt], a0, a1, a2, a3, b0[nt], b1[nt]);
            }
        }
        __syncthreads();
    }

    CP_WAIT0();
    __syncthreads();

    // =================== epilogue ===================
    float* Ds = sm;                         // 128 x PD floats (36 KB)

    if (kg == 0) {
        #pragma unroll
        for (int mt = 0; mt < 2; mt++) {
            int ml = mg * 32 + mt * 16 + qid;
            #pragma unroll
            for (int nt = 0; nt < 8; nt++) {
                int bb = nt * 8 + 2 * quad;
                Ds[ml * PD + bb]           = acc[mt][nt][0];
                Ds[ml * PD + bb + 1]       = acc[mt][nt][1];
                Ds[(ml + 8) * PD + bb]     = acc[mt][nt][2];
                Ds[(ml + 8) * PD + bb + 1] = acc[mt][nt][3];
            }
        }
    }
    __syncthreads();
    if (kg == 1) {
        #pragma unroll
        for (int mt = 0; mt < 2; mt++) {
            int ml = mg * 32 + mt * 16 + qid;
            #pragma unroll
            for (int nt = 0; nt < 8; nt++) {
                int bb = nt * 8 + 2 * quad;
                Ds[ml * PD + bb]           += acc[mt][nt][0];
                Ds[ml * PD + bb + 1]       += acc[mt][nt][1];
                Ds[(ml + 8) * PD + bb]     += acc[mt][nt][2];
                Ds[(ml + 8) * PD + bb + 1] += acc[mt][nt][3];
            }
        }
    }
    __syncthreads();

    // column reduction: thread owns (b = tid&63, m-quarter = tid>>6) over 32 m's
    float* sout = sm + MT * PD;             // 192 floats scratch
    if (tid < 192) sout[tid] = 0.0f;

    {
        const int bb = tid & 63;
        const int mq = tid >> 6;
        const float* argb = arg + bb * STRIDE;
        float po0 = 0.f, po1 = 0.f, po2 = 0.f;
        #pragma unroll 4
        for (int mm = 0; mm < 32; mm++) {
            int ml = mq * 32 + mm;
            int m = m0 + ml;
            unsigned j = (unsigned)m / 3u;
            int k = m - 3 * (int)j;
            float t = Ds[ml * PD + bb] * __ldg(argb + j);
            if (k == 0) po0 += t;
            else if (k == 1) po1 += t;
            else po2 += t;
        }
        __syncthreads();
        atomicAdd(&sout[bb * 3 + 0], po0);
        atomicAdd(&sout[bb * 3 + 1], po1);
        atomicAdd(&sout[bb * 3 + 2], po2);
    }
    __syncthreads();
    if (tid < 192) atomicAdd(&out[tid], sout[tid]);
}

// ---------------------------------------------------------------------------
extern "C" void kernel_launch(void* const* d_in, const int* in_sizes, int n_in,
                              void* d_out, int out_size) {
    const float* func = (const float*)d_in[0];
    const float* arg  = (const float*)d_in[1];
    const float* cooc = (const float*)d_in[2];
    float* out = (float*)d_out;

    cudaFuncSetAttribute(cooc_mma, cudaFuncAttributeMaxDynamicSharedMemorySize, SMEM_DYN);

    prep_kernel<<<(V * NB) / 256, 256>>>(func, out);
    cooc_mma<<<GRID, 256, SMEM_DYN>>>(cooc, arg, out);
}